// round 16
// baseline (speedup 1.0000x reference)
#include <cuda_runtime.h>

#define NN 100000
#define NE 1000000
#define DD 64
#define HH 64

// Scratch: aggregated messages mi[N][64] (25.6 MB). Static device global (no allocs allowed).
__device__ __align__(16) float g_mi[NN * DD];

// ---------------------------------------------------------------------------
// Kernel 1: zero the message buffer (vectorized).
// ---------------------------------------------------------------------------
__global__ void zero_kernel() {
    int i = blockIdx.x * blockDim.x + threadIdx.x;
    float4* p = (float4*)g_mi;
    if (i < NN * DD / 4) p[i] = make_float4(0.f, 0.f, 0.f, 0.f);
}

// ---------------------------------------------------------------------------
// Kernel 2: symmetric weighted scatter.
//   mi[t] += w * x[s];  mi[s] += w * x[t]
// One warp per edge: lanes 0-15 handle s->t (16 float4 chunks of the 64-float
// row), lanes 16-31 handle t->s. red.global.add.v4.f32 = fire-and-forget
// vector atomic (sm_90+), no return value -> no long-scoreboard stall.
// ---------------------------------------------------------------------------
__global__ void __launch_bounds__(256) scatter_kernel(
    const float* __restrict__ x,
    const float* __restrict__ ew,
    const int*   __restrict__ ei)
{
    int gtid  = blockIdx.x * blockDim.x + threadIdx.x;
    int warp  = gtid >> 5;
    int lane  = threadIdx.x & 31;
    int nwarp = (gridDim.x * blockDim.x) >> 5;

    const float4* x4  = (const float4*)x;
    float4*       mi4 = (float4*)g_mi;

    int half = lane >> 4;     // 0: x[s] -> mi[t],  1: x[t] -> mi[s]
    int c    = lane & 15;     // float4 chunk within the 64-float row

    for (int e = warp; e < NE; e += nwarp) {
        int   s = __ldg(ei + e);
        int   t = __ldg(ei + NE + e);
        float w = __ldg(ew + e);
        int src = half ? t : s;
        int dst = half ? s : t;
        float4 v = __ldg(x4 + src * 16 + c);
        float4* p = mi4 + dst * 16 + c;
        asm volatile("red.global.add.v4.f32 [%0], {%1, %2, %3, %4};"
                     :: "l"(p), "f"(v.x * w), "f"(v.y * w), "f"(v.z * w), "f"(v.w * w)
                     : "memory");
    }
}

// ---------------------------------------------------------------------------
// Kernel 3: fused MLP. One thread = one node. h and accumulators live in
// registers; W1 (32KB) + W2 (16KB) staged in 48KB static SMEM (broadcast
// LDS.128, conflict-free); W3 read via uniform __ldg float4 (L1-hit broadcast).
// ---------------------------------------------------------------------------
__device__ __forceinline__ void fma16(float h[64], float v, const float4* __restrict__ w) {
#pragma unroll
    for (int j4 = 0; j4 < 16; j4++) {
        float4 ww = w[j4];
        h[4 * j4 + 0] += v * ww.x;
        h[4 * j4 + 1] += v * ww.y;
        h[4 * j4 + 2] += v * ww.z;
        h[4 * j4 + 3] += v * ww.w;
    }
}

__device__ __forceinline__ void ln_tanh(float h[64],
                                        const float* __restrict__ b,
                                        const float* __restrict__ g,
                                        const float* __restrict__ be)
{
    float mu = 0.f;
#pragma unroll
    for (int j = 0; j < 64; j++) { h[j] += __ldg(b + j); mu += h[j]; }
    mu *= (1.f / 64.f);
    float var = 0.f;
#pragma unroll
    for (int j = 0; j < 64; j++) { float d = h[j] - mu; var += d * d; }
    var *= (1.f / 64.f);
    float inv = rsqrtf(var + 1e-5f);
#pragma unroll
    for (int j = 0; j < 64; j++) {
        h[j] = tanhf((h[j] - mu) * inv * __ldg(g + j) + __ldg(be + j));
    }
}

__global__ void __launch_bounds__(128) mlp_kernel(
    const float* __restrict__ x,
    const float* __restrict__ W1, const float* __restrict__ b1,
    const float* __restrict__ g1, const float* __restrict__ be1,
    const float* __restrict__ W2, const float* __restrict__ b2,
    const float* __restrict__ g2, const float* __restrict__ be2,
    const float* __restrict__ W3, const float* __restrict__ b3,
    float* __restrict__ out)
{
    __shared__ float4 sW1[128 * 16];   // 32 KB
    __shared__ float4 sW2[64 * 16];    // 16 KB  (total = 48 KB static, at the limit)

    int tid = threadIdx.x;
    const float4* W1_4 = (const float4*)W1;
    const float4* W2_4 = (const float4*)W2;
    for (int i = tid; i < 128 * 16; i += blockDim.x) sW1[i] = W1_4[i];
    for (int i = tid; i < 64 * 16; i += blockDim.x)  sW2[i] = W2_4[i];
    __syncthreads();

    int node = blockIdx.x * blockDim.x + tid;
    if (node >= NN) return;

    // ---- layer 1: h = [mi, x] @ W1 ----
    float h[64];
#pragma unroll
    for (int j = 0; j < 64; j++) h[j] = 0.f;

    const float4* in4 = (const float4*)(g_mi + node * 64);
#pragma unroll 4
    for (int k4 = 0; k4 < 16; k4++) {
        float4 v = in4[k4];
        fma16(h, v.x, sW1 + (k4 * 4 + 0) * 16);
        fma16(h, v.y, sW1 + (k4 * 4 + 1) * 16);
        fma16(h, v.z, sW1 + (k4 * 4 + 2) * 16);
        fma16(h, v.w, sW1 + (k4 * 4 + 3) * 16);
    }
    const float4* xv = (const float4*)(x + node * 64);
#pragma unroll 4
    for (int k4 = 0; k4 < 16; k4++) {
        float4 v = xv[k4];
        fma16(h, v.x, sW1 + (64 + k4 * 4 + 0) * 16);
        fma16(h, v.y, sW1 + (64 + k4 * 4 + 1) * 16);
        fma16(h, v.z, sW1 + (64 + k4 * 4 + 2) * 16);
        fma16(h, v.w, sW1 + (64 + k4 * 4 + 3) * 16);
    }
    ln_tanh(h, b1, g1, be1);

    // ---- layer 2 ----
    float h2[64];
#pragma unroll
    for (int j = 0; j < 64; j++) h2[j] = 0.f;
#pragma unroll 4
    for (int k = 0; k < 64; k++) fma16(h2, h[k], sW2 + k * 16);
    ln_tanh(h2, b2, g2, be2);

    // ---- layer 3: out = h2 @ W3 + b3 (W3 via uniform L1-broadcast loads) ----
    float o[64];
#pragma unroll
    for (int j = 0; j < 64; j++) o[j] = __ldg(b3 + j);
    const float4* W3_4 = (const float4*)W3;
#pragma unroll 2
    for (int k = 0; k < 64; k++) {
        float v = h2[k];
#pragma unroll
        for (int j4 = 0; j4 < 16; j4++) {
            float4 w = __ldg(W3_4 + k * 16 + j4);
            o[4 * j4 + 0] += v * w.x;
            o[4 * j4 + 1] += v * w.y;
            o[4 * j4 + 2] += v * w.z;
            o[4 * j4 + 3] += v * w.w;
        }
    }

    float4* out4 = (float4*)(out + node * 64);
#pragma unroll
    for (int j4 = 0; j4 < 16; j4++)
        out4[j4] = make_float4(o[4 * j4 + 0], o[4 * j4 + 1], o[4 * j4 + 2], o[4 * j4 + 3]);
}

// ---------------------------------------------------------------------------
// Launch. Inputs (metadata order):
//  0:x(N*64) 1:e(E) 2:edge_index(2*E i32) 3:W1(128*64) 4:b1 5:g1 6:be1
//  7:W2(64*64) 8:b2 9:g2 10:be2 11:W3(64*64) 12:b3  -> out (N*64 f32)
// ---------------------------------------------------------------------------
extern "C" void kernel_launch(void* const* d_in, const int* in_sizes, int n_in,
                              void* d_out, int out_size) {
    const float* x   = (const float*)d_in[0];
    const float* ew  = (const float*)d_in[1];
    const int*   ei  = (const int*)d_in[2];
    const float* W1  = (const float*)d_in[3];
    const float* b1  = (const float*)d_in[4];
    const float* g1  = (const float*)d_in[5];
    const float* be1 = (const float*)d_in[6];
    const float* W2  = (const float*)d_in[7];
    const float* b2  = (const float*)d_in[8];
    const float* g2  = (const float*)d_in[9];
    const float* be2 = (const float*)d_in[10];
    const float* W3  = (const float*)d_in[11];
    const float* b3  = (const float*)d_in[12];
    float* out = (float*)d_out;

    int n4 = NN * DD / 4;
    zero_kernel<<<(n4 + 255) / 256, 256>>>();
    scatter_kernel<<<2048, 256>>>(x, ew, ei);
    mlp_kernel<<<(NN + 127) / 128, 128>>>(x, W1, b1, g1, be1,
                                          W2, b2, g2, be2, W3, b3, out);
}